// round 6
// baseline (speedup 1.0000x reference)
#include <cuda_runtime.h>
#include <cuda_bf16.h>
#include <cstdint>
#include <math.h>

// ============================================================================
// Problem dims (fixed by the dataset): x [2,4096,4096] -> T=8192 tokens
// ============================================================================
#define T_TOK 8192
#define H_DIM 4096
#define I_DIM 2048

// NOTE: harness ptxas targets plain sm_103 (no 'a'), so tcgen05/TMEM are
// unavailable. Baseline-ISA tensor path: mma.sync (HMMA) + ldmatrix + cp.async.
//
// Numerics model (XLA CPU, default fast-math = arcp+contract):
//  - scale = amax / 127  lowers to  amax * RN(1/127)   (InstCombine arcp)
//  - q = xs / scale      lowers to  xs * (1.0/scale)   (reciprocal hoisted,
//                                   reciprocal itself an exact RN division)
//  - tanh = Eigen/XLA EmitFastTanh rational poly, FMA-contracted on x86
//  - logistic(x) = 0.5 + 0.5*tanh(0.5x)  ->  fma(0.5, t, 0.5)
// All replicated below with contraction-immune intrinsics.

static __device__ __forceinline__ float rcp127() { return 1.0f / 127.0f; } // folded RN const

// ============================================================================
// XLA EmitFastTanh replica, FMA-contracted form (matches x86 vfmadd codegen)
// ============================================================================
__device__ __forceinline__ float xla_fast_tanh(float x) {
    const float kMax = 7.90531110763549805f;
    float cl = fminf(fmaxf(x, -kMax), kMax);
    float x2 = __fmul_rn(cl, cl);
    float p = -2.76076847742355e-16f;                  // alpha_13
    p = __fmaf_rn(x2, p, 2.00018790482477e-13f);       // alpha_11
    p = __fmaf_rn(x2, p, -8.60467152213735e-11f);      // alpha_9
    p = __fmaf_rn(x2, p, 5.12229709037114e-08f);       // alpha_7
    p = __fmaf_rn(x2, p, 1.48572235717979e-05f);       // alpha_5
    p = __fmaf_rn(x2, p, 6.37261928875436e-04f);       // alpha_3
    p = __fmaf_rn(x2, p, 4.89352455891786e-03f);       // alpha_1
    p = __fmul_rn(cl, p);
    float q = 1.19825839466702e-06f;                   // beta_6
    q = __fmaf_rn(x2, q, 1.18534705686654e-04f);       // beta_4
    q = __fmaf_rn(x2, q, 2.26843463243900e-03f);       // beta_2
    q = __fmaf_rn(x2, q, 4.89352518554385e-03f);       // beta_0
    return (fabsf(x) < 0.0004f) ? x : __fdiv_rn(p, q);
}

__device__ __forceinline__ float xla_silu(float x) {
    float t = xla_fast_tanh(__fmul_rn(0.5f, x));
    float sig = __fmaf_rn(0.5f, t, 0.5f);   // 0.5 + 0.5*t, contracted
    return __fmul_rn(x, sig);
}

// ============================================================================
// PTX helpers
// ============================================================================
__device__ __forceinline__ uint32_t smem_to_u32(const void* smem_ptr) {
    uint32_t addr;
    asm("{ .reg .u64 tmp; cvta.to.shared.u64 tmp, %1; cvt.u32.u64 %0, tmp; }"
        : "=r"(addr) : "l"(smem_ptr));
    return addr;
}

#define SMEM_SWIZZLE_128B(byte_offset) \
    ((uint32_t)(byte_offset) ^ ((((uint32_t)(byte_offset)) >> 3) & 0x70u))

#define CP_ASYNC_16(smem_u32, gptr) \
    asm volatile("cp.async.cg.shared.global [%0], [%1], 16;" \
        :: "r"(smem_u32), "l"(gptr) : "memory")

#define CP_ASYNC_COMMIT() asm volatile("cp.async.commit_group;" ::: "memory")
#define CP_ASYNC_WAIT_1() asm volatile("cp.async.wait_group 1;" ::: "memory")

__device__ __forceinline__ void ldsm_x4(uint32_t& r0, uint32_t& r1,
                                        uint32_t& r2, uint32_t& r3,
                                        uint32_t smem_addr) {
    asm volatile(
        "ldmatrix.sync.aligned.m8n8.x4.shared.b16 {%0,%1,%2,%3}, [%4];"
        : "=r"(r0), "=r"(r1), "=r"(r2), "=r"(r3)
        : "r"(smem_addr));
}

__device__ __forceinline__ void mma16816(float* c, const uint32_t* a,
                                         uint32_t b0, uint32_t b1) {
    asm volatile(
        "mma.sync.aligned.m16n8k16.row.col.f32.bf16.bf16.f32 "
        "{%0,%1,%2,%3}, {%4,%5,%6,%7}, {%8,%9}, {%0,%1,%2,%3};"
        : "+f"(c[0]), "+f"(c[1]), "+f"(c[2]), "+f"(c[3])
        : "r"(a[0]), "r"(a[1]), "r"(a[2]), "r"(a[3]), "r"(b0), "r"(b1));
}

// ============================================================================
// Device scratch (static globals: allocation-guard-safe)
// ============================================================================
__device__ __nv_bfloat16 g_qg[(size_t)T_TOK * H_DIM];     // quantized x for gate
__device__ __nv_bfloat16 g_qu[(size_t)T_TOK * H_DIM];     // quantized x for up
__device__ __nv_bfloat16 g_wg[(size_t)I_DIM * H_DIM];     // w_gate bf16
__device__ __nv_bfloat16 g_wu[(size_t)I_DIM * H_DIM];     // w_up bf16
__device__ __nv_bfloat16 g_wd[(size_t)H_DIM * I_DIM];     // w_down bf16
__device__ float g_gate[(size_t)T_TOK * I_DIM];           // gate_out fp32
__device__ float g_up[(size_t)T_TOK * I_DIM];             // up_out fp32
__device__ __nv_bfloat16 g_qi[(size_t)T_TOK * I_DIM];     // quantized inter
__device__ float g_sg[T_TOK];
__device__ float g_su[T_TOK];
__device__ float g_si[T_TOK];

// ============================================================================
// Kernel 0: f32 -> bf16 convert (weights hold exact small ints)
// ============================================================================
__global__ void cvt_f32_bf16_kernel(const float* __restrict__ in,
                                    __nv_bfloat16* __restrict__ out, int n)
{
    int i = blockIdx.x * blockDim.x + threadIdx.x;
    int stride = gridDim.x * blockDim.x;
    for (; i < n; i += stride) out[i] = __float2bfloat16(in[i]);
}

// ============================================================================
// Kernel 1: per-token dual dynamic quant of x (gate + up smoothing vectors)
// scale = fmax(amax * RN(1/127), 1e-8); q = rint(xs * (1.0/scale)_RN)
// ============================================================================
__global__ void __launch_bounds__(256) quant_x_kernel(
    const float* __restrict__ x,
    const float* __restrict__ invg,
    const float* __restrict__ invu,
    __nv_bfloat16* __restrict__ qg,
    __nv_bfloat16* __restrict__ qu,
    float* __restrict__ sg,
    float* __restrict__ su)
{
    __shared__ __nv_bfloat16 xb[H_DIM];
    __shared__ float red_g[8];
    __shared__ float red_u[8];

    int row = blockIdx.x;
    const float* xr = x + (size_t)row * H_DIM;

    float amg = 0.f, amu = 0.f;
    for (int i = threadIdx.x; i < H_DIM; i += 256) {
        __nv_bfloat16 b = __float2bfloat16(xr[i]);   // x_flat = bf16(x)
        xb[i] = b;
        float f = __bfloat162float(b);
        amg = fmaxf(amg, fabsf(__fmul_rn(f, invg[i])));
        amu = fmaxf(amu, fabsf(__fmul_rn(f, invu[i])));
    }
    #pragma unroll
    for (int o = 16; o > 0; o >>= 1) {
        amg = fmaxf(amg, __shfl_xor_sync(0xffffffffu, amg, o));
        amu = fmaxf(amu, __shfl_xor_sync(0xffffffffu, amu, o));
    }
    int w = threadIdx.x >> 5;
    if ((threadIdx.x & 31) == 0) { red_g[w] = amg; red_u[w] = amu; }
    __syncthreads();
    if (threadIdx.x == 0) {
        float mg = red_g[0], mu = red_u[0];
        #pragma unroll
        for (int i = 1; i < 8; i++) { mg = fmaxf(mg, red_g[i]); mu = fmaxf(mu, red_u[i]); }
        red_g[0] = mg; red_u[0] = mu;
    }
    __syncthreads();
    const float scg = fmaxf(__fmul_rn(red_g[0], rcp127()), 1e-8f);
    const float scu = fmaxf(__fmul_rn(red_u[0], rcp127()), 1e-8f);
    if (threadIdx.x == 0) { sg[row] = scg; su[row] = scu; }

    const float rscg = __fdiv_rn(1.0f, scg);
    const float rscu = __fdiv_rn(1.0f, scu);
    for (int i = threadIdx.x; i < H_DIM; i += 256) {
        float f = __bfloat162float(xb[i]);
        float qgv = rintf(__fmul_rn(__fmul_rn(f, invg[i]), rscg));
        qgv = fminf(fmaxf(qgv, -127.f), 127.f);
        qg[(size_t)row * H_DIM + i] = __float2bfloat16(qgv);
        float quv = rintf(__fmul_rn(__fmul_rn(f, invu[i]), rscu));
        quv = fminf(fmaxf(quv, -127.f), 127.f);
        qu[(size_t)row * H_DIM + i] = __float2bfloat16(quv);
    }
}

// ============================================================================
// Kernel 2: HMMA bf16 GEMM,  C[m,n] = (sum_k A[m,k]*B[n,k]) * aS[m] * bS[n]
// CTA tile 128x128, K-chunk 64, double-buffered cp.async, 256 threads (8 warps:
// 4(M) x 2(N), warp tile 32x64). SW128-swizzled smem (conflict-free ldmatrix).
// Integer-valued operands -> fp32 accumulation exact in any order.
// ============================================================================
#define KC 64
#define STAGE_BYTES 32768        // A 16KB + B 16KB
#define GEMM_SMEM_BYTES 65536    // 2 stages

__global__ void __launch_bounds__(256)
gemm_bf16_mma(const __nv_bfloat16* __restrict__ A,   // [M,K] row-major
              const __nv_bfloat16* __restrict__ B,   // [N,K] row-major
              const float* __restrict__ aScale,      // [M]
              const float* __restrict__ bScale,      // [N]
              float* __restrict__ C,                 // [M,N] row-major
              int M, int N, int K)
{
    extern __shared__ __align__(1024) char sm[];
    const uint32_t sbase = smem_to_u32(sm);
    const uint32_t SA = 0, SB = 16384;

    const int tid = threadIdx.x;
    const int wid = tid >> 5, lid = tid & 31;
    const int m0 = blockIdx.y * 128;
    const int n0 = blockIdx.x * 128;
    const int wm = (wid & 3) * 32;   // warp M offset within tile
    const int wn = (wid >> 2) * 64;  // warp N offset within tile

    const int nChunks = K / KC;

    auto load_chunk = [&](int ch, int st) {
        const int k0 = ch * KC;
        const uint32_t stoff = sbase + (uint32_t)st * STAGE_BYTES;
        #pragma unroll
        for (int j = 0; j < 4; j++) {
            int i = tid + j * 256;
            int r = i >> 3, c = i & 7;
            uint32_t sw = SMEM_SWIZZLE_128B(r * 128 + c * 16);
            CP_ASYNC_16(stoff + SA + sw, A + (size_t)(m0 + r) * K + k0 + c * 8);
            CP_ASYNC_16(stoff + SB + sw, B + (size_t)(n0 + r) * K + k0 + c * 8);
        }
    };

    float acc[2][8][4];
    #pragma unroll
    for (int t = 0; t < 2; t++)
        #pragma unroll
        for (int n = 0; n < 8; n++)
            #pragma unroll
            for (int v = 0; v < 4; v++) acc[t][n][v] = 0.f;

    load_chunk(0, 0); CP_ASYNC_COMMIT();
    load_chunk(1, 1); CP_ASYNC_COMMIT();

    const int lrow = lid & 15;            // row within 16-row ldmatrix block
    const int lhalf = (lid >> 4) * 16;    // 16B half select

    for (int ch = 0; ch < nChunks; ch++) {
        CP_ASYNC_WAIT_1();
        __syncthreads();

        const uint32_t stoff = sbase + (uint32_t)(ch & 1) * STAGE_BYTES;
        #pragma unroll
        for (int s = 0; s < 4; s++) {            // 4 x k16 steps per 64-chunk
            const uint32_t kb = (uint32_t)(s * 32 + lhalf);
            uint32_t a[2][4];
            #pragma unroll
            for (int t = 0; t < 2; t++) {
                uint32_t off = SMEM_SWIZZLE_128B((uint32_t)(wm + t * 16 + lrow) * 128 + kb);
                ldsm_x4(a[t][0], a[t][1], a[t][2], a[t][3], stoff + SA + off);
            }
            uint32_t b[8][2];
            #pragma unroll
            for (int p = 0; p < 4; p++) {
                uint32_t off = SMEM_SWIZZLE_128B((uint32_t)(wn + p * 16 + lrow) * 128 + kb);
                uint32_t m0r, m1r, m2r, m3r;
                ldsm_x4(m0r, m1r, m2r, m3r, stoff + SB + off);
                b[2 * p][0] = m0r;     b[2 * p][1] = m2r;      // n rows 0-7 of pair
                b[2 * p + 1][0] = m1r; b[2 * p + 1][1] = m3r;  // n rows 8-15
            }
            #pragma unroll
            for (int t = 0; t < 2; t++)
                #pragma unroll
                for (int n = 0; n < 8; n++)
                    mma16816(acc[t][n], a[t], b[n][0], b[n][1]);
        }
        __syncthreads();
        if (ch + 2 < nChunks) load_chunk(ch + 2, ch & 1);
        CP_ASYNC_COMMIT();
    }

    // Epilogue with fused scales: C = acc * aS[m] * bS[n] (left-assoc, RN muls)
    #pragma unroll
    for (int t = 0; t < 2; t++) {
        const int r_lo = m0 + wm + t * 16 + (lid >> 2);
        const float s_lo = aScale[r_lo];
        const float s_hi = aScale[r_lo + 8];
        float* C_lo = C + (size_t)r_lo * N + n0 + wn;
        float* C_hi = C + (size_t)(r_lo + 8) * N + n0 + wn;
        #pragma unroll
        for (int n = 0; n < 8; n++) {
            const int colb = n * 8 + 2 * (lid & 3);
            const float b0 = bScale[n0 + wn + colb];
            const float b1 = bScale[n0 + wn + colb + 1];
            float2 vlo = make_float2(__fmul_rn(__fmul_rn(acc[t][n][0], s_lo), b0),
                                     __fmul_rn(__fmul_rn(acc[t][n][1], s_lo), b1));
            float2 vhi = make_float2(__fmul_rn(__fmul_rn(acc[t][n][2], s_hi), b0),
                                     __fmul_rn(__fmul_rn(acc[t][n][3], s_hi), b1));
            *(float2*)(C_lo + colb) = vlo;
            *(float2*)(C_hi + colb) = vhi;
        }
    }
}

// ============================================================================
// Kernel 3: SwiGLU (XLA tanh-form silu, FMA poly) + clip + bf16 + requant
// scale = fmax(amax * RN(1/127), 1e-8); q = rint(xs * (1.0/scale)_RN)
// ============================================================================
__global__ void __launch_bounds__(256) swiglu_quant_kernel(
    const float* __restrict__ gate,
    const float* __restrict__ up,
    const float* __restrict__ invi,
    __nv_bfloat16* __restrict__ qi,
    float* __restrict__ si)
{
    __shared__ __nv_bfloat16 ib[I_DIM];
    __shared__ float red[8];

    int row = blockIdx.x;
    const float* gr = gate + (size_t)row * I_DIM;
    const float* ur = up + (size_t)row * I_DIM;

    float am = 0.f;
    for (int i = threadIdx.x; i < I_DIM; i += 256) {
        float g = gr[i], u = ur[i];
        float v = __fmul_rn(xla_silu(g), u);   // silu(gate) * up, RN
        v = fminf(fmaxf(v, -10.0f), 10.0f);    // SWIGLU_LIMIT clip
        __nv_bfloat16 b = __float2bfloat16(v);
        ib[i] = b;
        am = fmaxf(am, fabsf(__fmul_rn(__bfloat162float(b), invi[i])));
    }
    #pragma unroll
    for (int o = 16; o > 0; o >>= 1)
        am = fmaxf(am, __shfl_xor_sync(0xffffffffu, am, o));
    int w = threadIdx.x >> 5;
    if ((threadIdx.x & 31) == 0) red[w] = am;
    __syncthreads();
    if (threadIdx.x == 0) {
        float m = red[0];
        #pragma unroll
        for (int i = 1; i < 8; i++) m = fmaxf(m, red[i]);
        red[0] = m;
    }
    __syncthreads();
    const float sc = fmaxf(__fmul_rn(red[0], rcp127()), 1e-8f);
    if (threadIdx.x == 0) si[row] = sc;
    const float rsc = __fdiv_rn(1.0f, sc);
    for (int i = threadIdx.x; i < I_DIM; i += 256) {
        float q = rintf(__fmul_rn(__fmul_rn(__bfloat162float(ib[i]), invi[i]), rsc));
        q = fminf(fmaxf(q, -127.f), 127.f);
        qi[(size_t)row * I_DIM + i] = __float2bfloat16(q);
    }
}

// ============================================================================
// Launch
// ============================================================================
extern "C" void kernel_launch(void* const* d_in, const int* in_sizes, int n_in,
                              void* d_out, int out_size)
{
    const float* x       = (const float*)d_in[0];
    const float* w_gate  = (const float*)d_in[1];
    const float* s_wgate = (const float*)d_in[2];
    const float* w_up    = (const float*)d_in[3];
    const float* s_wup   = (const float*)d_in[4];
    const float* w_down  = (const float*)d_in[5];
    const float* s_wdown = (const float*)d_in[6];
    const float* inv_g   = (const float*)d_in[7];
    const float* inv_u   = (const float*)d_in[8];
    const float* inv_i   = (const float*)d_in[9];
    float* out = (float*)d_out;

    void *p_qg, *p_qu, *p_wg, *p_wu, *p_wd, *p_gate, *p_up, *p_qi, *p_sg, *p_su, *p_si;
    cudaGetSymbolAddress(&p_qg, g_qg);
    cudaGetSymbolAddress(&p_qu, g_qu);
    cudaGetSymbolAddress(&p_wg, g_wg);
    cudaGetSymbolAddress(&p_wu, g_wu);
    cudaGetSymbolAddress(&p_wd, g_wd);
    cudaGetSymbolAddress(&p_gate, g_gate);
    cudaGetSymbolAddress(&p_up, g_up);
    cudaGetSymbolAddress(&p_qi, g_qi);
    cudaGetSymbolAddress(&p_sg, g_sg);
    cudaGetSymbolAddress(&p_su, g_su);
    cudaGetSymbolAddress(&p_si, g_si);

    // Host-side attribute set (not a stream op; graph-capture safe).
    cudaFuncSetAttribute(gemm_bf16_mma,
                         cudaFuncAttributeMaxDynamicSharedMemorySize,
                         GEMM_SMEM_BYTES);

    // 0. weights -> bf16 (exact: values are small integers)
    cvt_f32_bf16_kernel<<<512, 256>>>(w_gate, (__nv_bfloat16*)p_wg, I_DIM * H_DIM);
    cvt_f32_bf16_kernel<<<512, 256>>>(w_up,   (__nv_bfloat16*)p_wu, I_DIM * H_DIM);
    cvt_f32_bf16_kernel<<<512, 256>>>(w_down, (__nv_bfloat16*)p_wd, H_DIM * I_DIM);

    // 1. dual dynamic quant of x
    quant_x_kernel<<<T_TOK, 256>>>(x, inv_g, inv_u,
                                   (__nv_bfloat16*)p_qg, (__nv_bfloat16*)p_qu,
                                   (float*)p_sg, (float*)p_su);

    // 2+3. gate & up GEMMs: [T,I] = [T,H] @ [I,H]^T
    dim3 grid1(I_DIM / 128, T_TOK / 128);
    gemm_bf16_mma<<<grid1, 256, GEMM_SMEM_BYTES>>>(
        (const __nv_bfloat16*)p_qg, (const __nv_bfloat16*)p_wg,
        (const float*)p_sg, s_wgate, (float*)p_gate, T_TOK, I_DIM, H_DIM);
    gemm_bf16_mma<<<grid1, 256, GEMM_SMEM_BYTES>>>(
        (const __nv_bfloat16*)p_qu, (const __nv_bfloat16*)p_wu,
        (const float*)p_su, s_wup, (float*)p_up, T_TOK, I_DIM, H_DIM);

    // 4. swiglu + clip + requant
    swiglu_quant_kernel<<<T_TOK, 256>>>((const float*)p_gate, (const float*)p_up,
                                        inv_i, (__nv_bfloat16*)p_qi, (float*)p_si);

    // 5. down GEMM straight into d_out: [T,H] = [T,I] @ [H,I]^T
    dim3 grid3(H_DIM / 128, T_TOK / 128);
    gemm_bf16_mma<<<grid3, 256, GEMM_SMEM_BYTES>>>(
        (const __nv_bfloat16*)p_qi, (const __nv_bfloat16*)p_wd,
        (const float*)p_si, s_wdown, out, T_TOK, H_DIM, I_DIM);
}